// round 13
// baseline (speedup 1.0000x reference)
#include <cuda_runtime.h>
#include <cstdint>

#define NN 2
#define CC 12
#define AA 5
#define HH 256
#define HP 512
#define NIMG (NN*CC*AA)         // 120
#define NPIX (HP*HP)            // 262144
#define PH 576                  // padded smem line (512 + 512/8)

#define SZ_X ((long)NN*AA*HH*HH)   // 655360
#define SZ_M ((long)CC*HH*HH)      // 786432
#define SZ_K ((long)AA*AA*HP*HP)   // 6553600

// Scratch: 125.8 + 52.4 + 10.5 = 188.7MB (< ~190MB module limit from R1-R4)
__device__ __align__(128) float2 g_bufA[(size_t)NIMG * HP * HH];  // [img][w][r]
__device__ __align__(128) float2 g_kT[(size_t)25 * NPIX];         // [ba][w][h]
__device__ __align__(128) float2 g_part[(size_t)2 * SZ_X];        // coil-half partials

__device__ __forceinline__ int brev9(int i) { return (int)(__brev((unsigned)i) >> 23); }
__device__ __forceinline__ int phys(int e)  { return e + (e >> 3); }

// 2-warp named barrier: syncs the 64-thread group owning one FFT array.
#define BAR64(id) asm volatile("bar.sync %0, 64;" :: "r"(id) : "memory")

// ---------------------------------------------------------------------------
// Radix-8 register phase, compile-time P (0,1,2), DIF, SKIP1.
// tw[t] = exp(-i*pi*t/256). isign=+1 forward (numpy), -1 inverse.
// SKIP1 (P==0 only): stage-1 (w==1) is folded into global load (forward) or
// store (inverse) via the zero-pad/crop structure — omit it here.
// ---------------------------------------------------------------------------
template<int P, bool DIF, bool SKIP1>
__device__ __forceinline__ void reg_fft_phase(float2* a, int lane,
                                              const float2* tw, float isign) {
    constexpr int str = (P == 0) ? 1 : ((P == 1) ? 8 : 64);
    int base;
    if (P == 0)      base = lane << 3;
    else if (P == 1) base = ((lane >> 3) << 6) | (lane & 7);
    else             base = lane;
    int b_lo = base & (str - 1);

    float2 r[8];
    #pragma unroll
    for (int m = 0; m < 8; m++) r[m] = a[phys(base + m * str)];

    #pragma unroll
    for (int ss = 0; ss < 3; ss++) {
        const int sub = DIF ? (2 - ss) : ss;
        const int s = 3 * P + sub + 1;          // global stage 1..9
        const int half_m = 1 << sub;
        #pragma unroll
        for (int q = 0; q < 4; q++) {
            int jm = q & (half_m - 1);
            int m0 = ((q ^ jm) << 1) + jm;
            int m1 = m0 + half_m;
            float2 A = r[m0], B = r[m1];
            if (P == 0 && sub == 0) {           // w == 1 (DIT==DIF)
                if (!SKIP1) {
                    r[m0] = make_float2(A.x + B.x, A.y + B.y);
                    r[m1] = make_float2(A.x - B.x, A.y - B.y);
                }
            } else {
                int j = jm * str + b_lo;
                float2 w = tw[(j << (9 - s)) & 255];
                w.y *= isign;
                if (!DIF) {
                    float2 t = make_float2(B.x * w.x - B.y * w.y, B.x * w.y + B.y * w.x);
                    r[m0] = make_float2(A.x + t.x, A.y + t.y);
                    r[m1] = make_float2(A.x - t.x, A.y - t.y);
                } else {
                    float2 d = make_float2(A.x - B.x, A.y - B.y);
                    r[m0] = make_float2(A.x + B.x, A.y + B.y);
                    r[m1] = make_float2(d.x * w.x - d.y * w.y, d.x * w.y + d.y * w.x);
                }
            }
        }
    }
    #pragma unroll
    for (int m = 0; m < 8; m++) a[phys(base + m * str)] = r[m];
}

// ---------------------------------------------------------------------------
// k_tr: tiled transpose kernels[ba][h][w] -> g_kT[ba][w][h]
// ---------------------------------------------------------------------------
__global__ void __launch_bounds__(256)
k_tr(const float* __restrict__ kr, const float* __restrict__ ki) {
    __shared__ float2 t[32][33];
    int ba = blockIdx.z;
    int tx = threadIdx.x & 31, ty = threadIdx.x >> 5;
    int h0 = blockIdx.y * 32, w0 = blockIdx.x * 32;
    #pragma unroll
    for (int k = 0; k < 4; k++) {
        size_t o = (size_t)ba * NPIX + (size_t)(h0 + ty + k * 8) * HP + w0 + tx;
        t[ty + k * 8][tx] = make_float2(kr[o], ki[o]);
    }
    __syncthreads();
    #pragma unroll
    for (int k = 0; k < 4; k++) {
        g_kT[(size_t)ba * NPIX + (size_t)(w0 + ty + k * 8) * HP + h0 + tx] = t[tx][ty + k * 8];
    }
}

// ---------------------------------------------------------------------------
// k_f1: row FFTs of padded x*mps, stage-1 folded into load (no zero fill).
// Block = (img, 4 rows). Output transposed g_bufA[img][w][r] via float4.
// ---------------------------------------------------------------------------
__global__ void __launch_bounds__(256)
k_f1(const float* __restrict__ xr, const float* __restrict__ xi,
     const float* __restrict__ mr, const float* __restrict__ mi) {
    __shared__ float2 d[4][PH];
    __shared__ float2 tw[256];
    int tid = threadIdx.x;
    { float sv, cv; sincospif(-(float)tid / 256.0f, &sv, &cv); tw[tid] = make_float2(cv, sv); }

    int img = blockIdx.x >> 6;
    int row0 = (blockIdx.x & 63) * 4;
    int a = img % AA, nc = img / AA, c = nc % CC, n = nc / CC;
    int row = tid >> 6, lane = tid & 63;
    int bar = row + 1;

    // folded stage-1 load: each input value fills its position-pair (both halves)
    size_t xoff = ((size_t)(n * AA + a) * HH + row0 + row) * HH;
    size_t moff = ((size_t)c * HH + row0 + row) * HH;
    #pragma unroll
    for (int k = 0; k < 4; k++) {
        int iw = lane + k * 64;
        float ar = xr[xoff + iw], ai = xi[xoff + iw];
        float br = mr[moff + iw], bi = mi[moff + iw];
        float2 v = make_float2(ar * br - ai * bi, ar * bi + ai * br);
        int p0 = brev9(128 + iw) & ~1;
        d[row][phys(p0)]     = v;
        d[row][phys(p0 + 1)] = (iw < 128) ? v : make_float2(-v.x, -v.y);
    }
    __syncthreads();   // tw visibility + all pair-writes done

    reg_fft_phase<0,false,true >(d[row], lane, tw, 1.f); BAR64(bar);
    reg_fft_phase<1,false,false>(d[row], lane, tw, 1.f); BAR64(bar);
    reg_fft_phase<2,false,false>(d[row], lane, tw, 1.f);
    __syncthreads();   // store reads all arrays

    for (int w = tid; w < 512; w += 256) {
        float2 v0 = d[0][phys(w)], v1 = d[1][phys(w)];
        float2 v2 = d[2][phys(w)], v3 = d[3][phys(w)];
        float4* p = (float4*)&g_bufA[((size_t)img * HP + w) * HH + row0];
        p[0] = make_float4(v0.x, v0.y, v1.x, v1.y);
        p[1] = make_float4(v2.x, v2.y, v3.x, v3.y);
    }
}

// ---------------------------------------------------------------------------
// k_fused: forward col FFT (stage-1 folded into load) + 5x5 mix + inverse
// col FFT (last stage folded into cropped store). 640 thr, 10 groups of 64.
// ---------------------------------------------------------------------------
__global__ void __launch_bounds__(640, 2)
k_fused() {
    __shared__ float2 d[10][PH];
    __shared__ float2 tw[256];
    int tid = threadIdx.x;
    if (tid < 256) { float sv, cv; sincospif(-(float)tid / 256.0f, &sv, &cv); tw[tid] = make_float2(cv, sv); }

    int bid = blockIdx.x;
    int nc = bid % (NN * CC);
    int w0 = (bid / (NN * CC)) * 2;

    int ac = tid >> 6, lane = tid & 63;
    int arr = ac >> 1, col = ac & 1;
    int img = nc * AA + arr;
    int bar = ac + 1;

    // folded stage-1 load (writes all 512 logical slots; no zero fill, no race)
    const float2* in = &g_bufA[((size_t)img * HP + w0 + col) * HH];
    #pragma unroll
    for (int k = 0; k < 4; k++) {
        int r = lane + k * 64;
        float2 v = in[r];
        int p0 = brev9(128 + r) & ~1;
        d[ac][phys(p0)]     = v;
        d[ac][phys(p0 + 1)] = (r < 128) ? v : make_float2(-v.x, -v.y);
    }
    __syncthreads();   // tw visibility + pair-writes

    reg_fft_phase<0,false,true >(d[ac], lane, tw, 1.f); BAR64(bar);
    reg_fft_phase<1,false,false>(d[ac], lane, tw, 1.f); BAR64(bar);
    reg_fft_phase<2,false,false>(d[ac], lane, tw, 1.f);
    __syncthreads();   // mix reads all arrays

    // mix: G[b](h,w) = sum_a K[b][a](h,w) * F[a](h,w)
    for (int i = tid; i < 2 * 512; i += 640) {
        int mcol = i >> 9, t = i & 511;
        size_t kbase = (size_t)(w0 + mcol) * HP + t;
        float2 F[5], G[5];
        #pragma unroll
        for (int a2 = 0; a2 < 5; a2++) F[a2] = d[a2 * 2 + mcol][phys(t)];
        #pragma unroll
        for (int b = 0; b < 5; b++) {
            float2 acc = make_float2(0.f, 0.f);
            #pragma unroll
            for (int a2 = 0; a2 < 5; a2++) {
                float2 K = g_kT[(size_t)(b * 5 + a2) * NPIX + kbase];
                acc.x += K.x * F[a2].x - K.y * F[a2].y;
                acc.y += K.x * F[a2].y + K.y * F[a2].x;
            }
            G[b] = acc;
        }
        #pragma unroll
        for (int b = 0; b < 5; b++) d[b * 2 + mcol][phys(t)] = G[b];
    }
    __syncthreads();   // inverse reads own array, written by any thread

    reg_fft_phase<2,true,false>(d[ac], lane, tw, -1.f); BAR64(bar);
    reg_fft_phase<1,true,false>(d[ac], lane, tw, -1.f); BAR64(bar);
    reg_fft_phase<0,true,true >(d[ac], lane, tw, -1.f); BAR64(bar);

    // folded last-stage cropped store: v(t=128+r) = A ± B over the pair
    const float sc = 1.0f / 512.0f;
    float2* outp = &g_bufA[((size_t)img * HP + w0 + col) * HH];
    #pragma unroll
    for (int k = 0; k < 4; k++) {
        int r = lane + k * 64;
        int p0 = brev9(128 + r) & ~1;
        float2 A = d[ac][phys(p0)], B = d[ac][phys(p0 + 1)];
        float2 v = (r < 128) ? make_float2(A.x + B.x, A.y + B.y)
                             : make_float2(A.x - B.x, A.y - B.y);
        outp[r] = make_float2(v.x * sc, v.y * sc);
    }
}

// ---------------------------------------------------------------------------
// k_i2: inverse row FFTs + folded crop + conj(mps) combine over a HALF of the
// coils (cg selects 6). Partial sums to g_part; k_comb finishes.
// Block = (cg, n, b, 4 rows); grid 1280 (2x parallelism, disjoint reads).
// ---------------------------------------------------------------------------
__global__ void __launch_bounds__(256)
k_i2(const float* __restrict__ mr, const float* __restrict__ mi) {
    __shared__ float2 d[4][PH];
    __shared__ float2 tw[256];
    int tid = threadIdx.x;
    { float sv, cv; sincospif(-(float)tid / 256.0f, &sv, &cv); tw[tid] = make_float2(cv, sv); }

    int bid = blockIdx.x;
    int row0 = (bid & 63) * 4;
    int cgnb = bid >> 6;
    int cg = cgnb & 1;
    int nb = cgnb >> 1;
    int b = nb % AA;
    int n = nb / AA;

    int row = tid >> 6, lane = tid & 63;
    int bar = row + 1;

    float2 acc[4];
    #pragma unroll
    for (int k = 0; k < 4; k++) acc[k] = make_float2(0.f, 0.f);

    for (int ci = 0; ci < 6; ci++) {
        int c = cg * 6 + ci;
        int img = (n * CC + c) * AA + b;
        __syncthreads();   // prior accum reads done (also tw on first iter)
        for (int w = tid; w < 512; w += 256) {
            const float4* p = (const float4*)&g_bufA[((size_t)img * HP + w) * HH + row0];
            float4 q0 = p[0], q1 = p[1];
            d[0][phys(w)] = make_float2(q0.x, q0.y);
            d[1][phys(w)] = make_float2(q0.z, q0.w);
            d[2][phys(w)] = make_float2(q1.x, q1.y);
            d[3][phys(w)] = make_float2(q1.z, q1.w);
        }
        __syncthreads();   // all-array writes visible

        reg_fft_phase<2,true,false>(d[row], lane, tw, -1.f); BAR64(bar);
        reg_fft_phase<1,true,false>(d[row], lane, tw, -1.f); BAR64(bar);
        reg_fft_phase<0,true,true >(d[row], lane, tw, -1.f); BAR64(bar);

        size_t moff = ((size_t)c * HH + row0 + row) * HH;
        #pragma unroll
        for (int k = 0; k < 4; k++) {
            int cw = lane + k * 64;
            int p0 = brev9(128 + cw) & ~1;
            float2 A = d[row][phys(p0)], B = d[row][phys(p0 + 1)];
            float2 v = (cw < 128) ? make_float2(A.x + B.x, A.y + B.y)
                                  : make_float2(A.x - B.x, A.y - B.y);
            float m_r = mr[moff + cw], m_i = mi[moff + cw];
            acc[k].x += v.x * m_r + v.y * m_i;   // v * conj(m)
            acc[k].y += v.y * m_r - v.x * m_i;
        }
    }

    size_t obase = ((size_t)(n * AA + b) * HH + row0 + row) * HH;
    #pragma unroll
    for (int k = 0; k < 4; k++) {
        g_part[(size_t)cg * SZ_X + obase + lane + k * 64] = acc[k];
    }
}

// ---------------------------------------------------------------------------
// k_comb: add the two coil-half partials, scale, write planar output.
// ---------------------------------------------------------------------------
__global__ void __launch_bounds__(256)
k_comb(float* __restrict__ out, long out_floats) {
    size_t o = (size_t)blockIdx.x * 256 + threadIdx.x;   // 0..SZ_X-1
    float2 v0 = g_part[o], v1 = g_part[(size_t)SZ_X + o];
    const float sc = 4.0f / 512.0f;   // OVERSAMP^2 * (1/512 ifft ortho)
    float re = (v0.x + v1.x) * sc;
    float im = (v0.y + v1.y) * sc;
    if ((long)o < out_floats) out[o] = re;                       // real plane
    if ((long)(SZ_X + o) < out_floats) out[SZ_X + o] = im;       // imag if room
}

// ---------------------------------------------------------------------------
// Input resolver (identical to R7/R9/R10/R12-passing version)
// ---------------------------------------------------------------------------
static void pick(void* const* d_in, const int* in_sizes, int n_in, long S,
                 int pos_split, const float** re, const float** im) {
    int idx[2] = {-1, -1};
    int cnt = 0;
    for (int i = 0; i < n_in; i++) {
        long v = (long)in_sizes[i];
        if (v == S || v == 2 * S || v == 4 * S || v == 8 * S) {
            if (cnt < 2) idx[cnt] = i;
            cnt++;
        }
    }
    if (cnt >= 2) {
        *re = (const float*)d_in[idx[0]];
        *im = (const float*)d_in[idx[1]];
    } else if (cnt == 1) {
        *re = (const float*)d_in[idx[0]];
        *im = *re + 1;
    } else {
        int p0 = (pos_split < n_in) ? pos_split : 0;
        int p1 = (pos_split + 1 < n_in) ? pos_split + 1 : p0;
        *re = (const float*)d_in[p0];
        *im = (const float*)d_in[p1];
    }
}

extern "C" void kernel_launch(void* const* d_in, const int* in_sizes, int n_in,
                              void* d_out, int out_size) {
    const float *xr, *xi, *mr, *mi, *kr, *ki;
    pick(d_in, in_sizes, n_in, SZ_X, 0, &xr, &xi);
    pick(d_in, in_sizes, n_in, SZ_M, 2, &mr, &mi);
    pick(d_in, in_sizes, n_in, SZ_K, 4, &kr, &ki);
    float* out = (float*)d_out;

    dim3 trg(16, 16, 25);
    k_tr<<<trg, 256>>>(kr, ki);
    k_f1<<<NIMG * 64, 256>>>(xr, xi, mr, mi);
    k_fused<<<(NN * CC) * (HP / 2), 640>>>();
    k_i2<<<NN * AA * 64 * 2, 256>>>(mr, mi);
    k_comb<<<(int)(SZ_X / 256), 256>>>(out, (long)out_size);
}

// round 14
// speedup vs baseline: 1.0433x; 1.0433x over previous
#include <cuda_runtime.h>
#include <cstdint>

#define NN 2
#define CC 12
#define AA 5
#define HH 256
#define HP 512
#define NIMG (NN*CC*AA)         // 120
#define NPIX (HP*HP)            // 262144
#define PH 576                  // padded smem line (512 + 512/8)

#define SZ_X ((long)NN*AA*HH*HH)   // 655360
#define SZ_M ((long)CC*HH*HH)      // 786432
#define SZ_K ((long)AA*AA*HP*HP)   // 6553600

// Scratch: 125.8 + 52.4 + 10.5 = 188.7MB (< ~190MB module limit from R1-R4)
__device__ __align__(128) float2 g_bufA[(size_t)NIMG * HP * HH];  // [img][w][r]
__device__ __align__(128) float2 g_kT[(size_t)25 * NPIX];         // [ba][w][h]
__device__ __align__(128) float2 g_part[(size_t)2 * SZ_X];        // coil-half partials

__device__ __forceinline__ int brev9(int i) { return (int)(__brev((unsigned)i) >> 23); }
__device__ __forceinline__ int phys(int e)  { return e + (e >> 3); }

// 2-warp named barrier: syncs the 64-thread group owning one FFT array.
#define BAR64(id) asm volatile("bar.sync %0, 64;" :: "r"(id) : "memory")

// ---------------------------------------------------------------------------
// Radix-8 register phase, compile-time P (0,1,2) and DIF.  (R12-exact)
// tw[t] = exp(-i*pi*t/256). isign=+1 forward (numpy), -1 inverse.
// P=0 first sub-stage: w == 1 -> twiddle-free butterflies (in registers).
// ---------------------------------------------------------------------------
template<int P, bool DIF>
__device__ __forceinline__ void reg_fft_phase(float2* a, int lane,
                                              const float2* tw, float isign) {
    constexpr int str = (P == 0) ? 1 : ((P == 1) ? 8 : 64);
    int base;
    if (P == 0)      base = lane << 3;
    else if (P == 1) base = ((lane >> 3) << 6) | (lane & 7);
    else             base = lane;
    int b_lo = base & (str - 1);

    float2 r[8];
    #pragma unroll
    for (int m = 0; m < 8; m++) r[m] = a[phys(base + m * str)];

    #pragma unroll
    for (int ss = 0; ss < 3; ss++) {
        const int sub = DIF ? (2 - ss) : ss;
        const int s = 3 * P + sub + 1;          // global stage 1..9
        const int half_m = 1 << sub;
        #pragma unroll
        for (int q = 0; q < 4; q++) {
            int jm = q & (half_m - 1);
            int m0 = ((q ^ jm) << 1) + jm;
            int m1 = m0 + half_m;
            float2 A = r[m0], B = r[m1];
            if (P == 0 && sub == 0) {           // w == 1 (DIT==DIF)
                r[m0] = make_float2(A.x + B.x, A.y + B.y);
                r[m1] = make_float2(A.x - B.x, A.y - B.y);
            } else {
                int j = jm * str + b_lo;
                float2 w = tw[(j << (9 - s)) & 255];
                w.y *= isign;
                if (!DIF) {
                    float2 t = make_float2(B.x * w.x - B.y * w.y, B.x * w.y + B.y * w.x);
                    r[m0] = make_float2(A.x + t.x, A.y + t.y);
                    r[m1] = make_float2(A.x - t.x, A.y - t.y);
                } else {
                    float2 d = make_float2(A.x - B.x, A.y - B.y);
                    r[m0] = make_float2(A.x + B.x, A.y + B.y);
                    r[m1] = make_float2(d.x * w.x - d.y * w.y, d.x * w.y + d.y * w.x);
                }
            }
        }
    }
    #pragma unroll
    for (int m = 0; m < 8; m++) a[phys(base + m * str)] = r[m];
}

// ---------------------------------------------------------------------------
// k_tr: tiled transpose kernels[ba][h][w] -> g_kT[ba][w][h]
// ---------------------------------------------------------------------------
__global__ void __launch_bounds__(256)
k_tr(const float* __restrict__ kr, const float* __restrict__ ki) {
    __shared__ float2 t[32][33];
    int ba = blockIdx.z;
    int tx = threadIdx.x & 31, ty = threadIdx.x >> 5;
    int h0 = blockIdx.y * 32, w0 = blockIdx.x * 32;
    #pragma unroll
    for (int k = 0; k < 4; k++) {
        size_t o = (size_t)ba * NPIX + (size_t)(h0 + ty + k * 8) * HP + w0 + tx;
        t[ty + k * 8][tx] = make_float2(kr[o], ki[o]);
    }
    __syncthreads();
    #pragma unroll
    for (int k = 0; k < 4; k++) {
        g_kT[(size_t)ba * NPIX + (size_t)(w0 + ty + k * 8) * HP + h0 + tx] = t[tx][ty + k * 8];
    }
}

// ---------------------------------------------------------------------------
// k_f1: row FFTs of padded x*mps. Block = (img, 4 rows). (R12-exact)
// ---------------------------------------------------------------------------
__global__ void __launch_bounds__(256)
k_f1(const float* __restrict__ xr, const float* __restrict__ xi,
     const float* __restrict__ mr, const float* __restrict__ mi) {
    __shared__ float2 d[4][PH];
    __shared__ float2 tw[256];
    int tid = threadIdx.x;
    { float sv, cv; sincospif(-(float)tid / 256.0f, &sv, &cv); tw[tid] = make_float2(cv, sv); }

    int img = blockIdx.x >> 6;
    int row0 = (blockIdx.x & 63) * 4;
    int a = img % AA, nc = img / AA, c = nc % CC, n = nc / CC;
    int row = tid >> 6, lane = tid & 63;
    int bar = row + 1;

    // group-local zero, barrier, scatter-load
    #pragma unroll
    for (int k = lane; k < PH; k += 64) d[row][k] = make_float2(0.f, 0.f);
    BAR64(bar);
    size_t xoff = ((size_t)(n * AA + a) * HH + row0 + row) * HH;
    size_t moff = ((size_t)c * HH + row0 + row) * HH;
    #pragma unroll
    for (int k = 0; k < 4; k++) {
        int iw = lane + k * 64;
        float ar = xr[xoff + iw], ai = xi[xoff + iw];
        float br = mr[moff + iw], bi = mi[moff + iw];
        d[row][phys(brev9(128 + iw))] = make_float2(ar * br - ai * bi, ar * bi + ai * br);
    }
    __syncthreads();

    reg_fft_phase<0,false>(d[row], lane, tw, 1.f); BAR64(bar);
    reg_fft_phase<1,false>(d[row], lane, tw, 1.f); BAR64(bar);
    reg_fft_phase<2,false>(d[row], lane, tw, 1.f);
    __syncthreads();

    for (int w = tid; w < 512; w += 256) {
        float2 v0 = d[0][phys(w)], v1 = d[1][phys(w)];
        float2 v2 = d[2][phys(w)], v3 = d[3][phys(w)];
        float4* p = (float4*)&g_bufA[((size_t)img * HP + w) * HH + row0];
        p[0] = make_float4(v0.x, v0.y, v1.x, v1.y);
        p[1] = make_float4(v2.x, v2.y, v3.x, v3.y);
    }
}

// ---------------------------------------------------------------------------
// k_fused: forward col FFT + 5x5 mix + inverse col FFT per (nc, 2-w tile).
// (R12-exact)
// ---------------------------------------------------------------------------
__global__ void __launch_bounds__(640, 2)
k_fused() {
    __shared__ float2 d[10][PH];
    __shared__ float2 tw[256];
    int tid = threadIdx.x;
    if (tid < 256) { float sv, cv; sincospif(-(float)tid / 256.0f, &sv, &cv); tw[tid] = make_float2(cv, sv); }

    int bid = blockIdx.x;
    int nc = bid % (NN * CC);
    int w0 = (bid / (NN * CC)) * 2;

    int ac = tid >> 6, lane = tid & 63;
    int arr = ac >> 1, col = ac & 1;
    int img = nc * AA + arr;
    int bar = ac + 1;

    #pragma unroll
    for (int k = lane; k < PH; k += 64) d[ac][k] = make_float2(0.f, 0.f);
    BAR64(bar);
    const float2* in = &g_bufA[((size_t)img * HP + w0 + col) * HH];
    #pragma unroll
    for (int k = 0; k < 4; k++) {
        int r = lane + k * 64;
        d[ac][phys(brev9(128 + r))] = in[r];
    }
    __syncthreads();

    reg_fft_phase<0,false>(d[ac], lane, tw, 1.f); BAR64(bar);
    reg_fft_phase<1,false>(d[ac], lane, tw, 1.f); BAR64(bar);
    reg_fft_phase<2,false>(d[ac], lane, tw, 1.f);
    __syncthreads();

    for (int i = tid; i < 2 * 512; i += 640) {
        int mcol = i >> 9, t = i & 511;
        size_t kbase = (size_t)(w0 + mcol) * HP + t;
        float2 F[5], G[5];
        #pragma unroll
        for (int a2 = 0; a2 < 5; a2++) F[a2] = d[a2 * 2 + mcol][phys(t)];
        #pragma unroll
        for (int b = 0; b < 5; b++) {
            float2 acc = make_float2(0.f, 0.f);
            #pragma unroll
            for (int a2 = 0; a2 < 5; a2++) {
                float2 K = g_kT[(size_t)(b * 5 + a2) * NPIX + kbase];
                acc.x += K.x * F[a2].x - K.y * F[a2].y;
                acc.y += K.x * F[a2].y + K.y * F[a2].x;
            }
            G[b] = acc;
        }
        #pragma unroll
        for (int b = 0; b < 5; b++) d[b * 2 + mcol][phys(t)] = G[b];
    }
    __syncthreads();

    reg_fft_phase<2,true>(d[ac], lane, tw, -1.f); BAR64(bar);
    reg_fft_phase<1,true>(d[ac], lane, tw, -1.f); BAR64(bar);
    reg_fft_phase<0,true>(d[ac], lane, tw, -1.f); BAR64(bar);

    const float sc = 1.0f / 512.0f;
    float2* outp = &g_bufA[((size_t)img * HP + w0 + col) * HH];
    #pragma unroll
    for (int k = 0; k < 4; k++) {
        int r = lane + k * 64;
        float2 v = d[ac][phys(brev9(128 + r))];
        outp[r] = make_float2(v.x * sc, v.y * sc);
    }
}

// ---------------------------------------------------------------------------
// k_i2: inverse row FFTs + crop + conj(mps) combine over HALF the coils
// (cg selects 6). R12 FFT/crop structure; partials to g_part.
// Block = (cg, n, b, 4 rows); grid 1280.
// ---------------------------------------------------------------------------
__global__ void __launch_bounds__(256)
k_i2(const float* __restrict__ mr, const float* __restrict__ mi) {
    __shared__ float2 d[4][PH];
    __shared__ float2 tw[256];
    int tid = threadIdx.x;
    { float sv, cv; sincospif(-(float)tid / 256.0f, &sv, &cv); tw[tid] = make_float2(cv, sv); }

    int bid = blockIdx.x;
    int row0 = (bid & 63) * 4;
    int cgnb = bid >> 6;
    int cg = cgnb & 1;
    int nb = cgnb >> 1;
    int b = nb % AA;
    int n = nb / AA;

    int row = tid >> 6, lane = tid & 63;
    int bar = row + 1;

    float2 acc[4];
    #pragma unroll
    for (int k = 0; k < 4; k++) acc[k] = make_float2(0.f, 0.f);

    for (int ci = 0; ci < 6; ci++) {
        int c = cg * 6 + ci;
        int img = (n * CC + c) * AA + b;
        __syncthreads();   // prior accum reads done (also tw on first iter)
        for (int w = tid; w < 512; w += 256) {
            const float4* p = (const float4*)&g_bufA[((size_t)img * HP + w) * HH + row0];
            float4 q0 = p[0], q1 = p[1];
            d[0][phys(w)] = make_float2(q0.x, q0.y);
            d[1][phys(w)] = make_float2(q0.z, q0.w);
            d[2][phys(w)] = make_float2(q1.x, q1.y);
            d[3][phys(w)] = make_float2(q1.z, q1.w);
        }
        __syncthreads();

        reg_fft_phase<2,true>(d[row], lane, tw, -1.f); BAR64(bar);
        reg_fft_phase<1,true>(d[row], lane, tw, -1.f); BAR64(bar);
        reg_fft_phase<0,true>(d[row], lane, tw, -1.f); BAR64(bar);

        size_t moff = ((size_t)c * HH + row0 + row) * HH;
        #pragma unroll
        for (int k = 0; k < 4; k++) {
            int cw = lane + k * 64;
            float2 v = d[row][phys(brev9(128 + cw))];
            float m_r = mr[moff + cw], m_i = mi[moff + cw];
            acc[k].x += v.x * m_r + v.y * m_i;   // v * conj(m)
            acc[k].y += v.y * m_r - v.x * m_i;
        }
    }

    size_t obase = ((size_t)(n * AA + b) * HH + row0 + row) * HH;
    #pragma unroll
    for (int k = 0; k < 4; k++) {
        g_part[(size_t)cg * SZ_X + obase + lane + k * 64] = acc[k];
    }
}

// ---------------------------------------------------------------------------
// k_comb: add the two coil-half partials, scale, write planar output.
// ---------------------------------------------------------------------------
__global__ void __launch_bounds__(256)
k_comb(float* __restrict__ out, long out_floats) {
    size_t o = (size_t)blockIdx.x * 256 + threadIdx.x;   // 0..SZ_X-1
    float2 v0 = g_part[o], v1 = g_part[(size_t)SZ_X + o];
    const float sc = 4.0f / 512.0f;   // OVERSAMP^2 * (1/512 ifft ortho)
    float re = (v0.x + v1.x) * sc;
    float im = (v0.y + v1.y) * sc;
    if ((long)o < out_floats) out[o] = re;                       // real plane
    if ((long)(SZ_X + o) < out_floats) out[SZ_X + o] = im;       // imag if room
}

// ---------------------------------------------------------------------------
// Input resolver (identical to R7/R9/R10/R12-passing version)
// ---------------------------------------------------------------------------
static void pick(void* const* d_in, const int* in_sizes, int n_in, long S,
                 int pos_split, const float** re, const float** im) {
    int idx[2] = {-1, -1};
    int cnt = 0;
    for (int i = 0; i < n_in; i++) {
        long v = (long)in_sizes[i];
        if (v == S || v == 2 * S || v == 4 * S || v == 8 * S) {
            if (cnt < 2) idx[cnt] = i;
            cnt++;
        }
    }
    if (cnt >= 2) {
        *re = (const float*)d_in[idx[0]];
        *im = (const float*)d_in[idx[1]];
    } else if (cnt == 1) {
        *re = (const float*)d_in[idx[0]];
        *im = *re + 1;
    } else {
        int p0 = (pos_split < n_in) ? pos_split : 0;
        int p1 = (pos_split + 1 < n_in) ? pos_split + 1 : p0;
        *re = (const float*)d_in[p0];
        *im = (const float*)d_in[p1];
    }
}

extern "C" void kernel_launch(void* const* d_in, const int* in_sizes, int n_in,
                              void* d_out, int out_size) {
    const float *xr, *xi, *mr, *mi, *kr, *ki;
    pick(d_in, in_sizes, n_in, SZ_X, 0, &xr, &xi);
    pick(d_in, in_sizes, n_in, SZ_M, 2, &mr, &mi);
    pick(d_in, in_sizes, n_in, SZ_K, 4, &kr, &ki);
    float* out = (float*)d_out;

    dim3 trg(16, 16, 25);
    k_tr<<<trg, 256>>>(kr, ki);
    k_f1<<<NIMG * 64, 256>>>(xr, xi, mr, mi);
    k_fused<<<(NN * CC) * (HP / 2), 640>>>();
    k_i2<<<NN * AA * 64 * 2, 256>>>(mr, mi);
    k_comb<<<(int)(SZ_X / 256), 256>>>(out, (long)out_size);
}

// round 15
// speedup vs baseline: 1.0472x; 1.0037x over previous
#include <cuda_runtime.h>
#include <cstdint>

#define NN 2
#define CC 12
#define AA 5
#define HH 256
#define HP 512
#define NIMG (NN*CC*AA)         // 120
#define NPIX (HP*HP)            // 262144
#define PH 576                  // padded smem line for 8pt kernels (512 + 64)
#define PH2 544                 // padded smem line for 16pt kernel (512 + 32)

#define SZ_X ((long)NN*AA*HH*HH)   // 655360
#define SZ_M ((long)CC*HH*HH)      // 786432
#define SZ_K ((long)AA*AA*HP*HP)   // 6553600

// Scratch: 125.8 + 52.4 + 10.5 = 188.7MB (< ~190MB module limit from R1-R4)
__device__ __align__(128) float2 g_bufA[(size_t)NIMG * HP * HH];  // [img][w][r]
__device__ __align__(128) float2 g_kT[(size_t)25 * NPIX];         // [ba][w][h]
__device__ __align__(128) float2 g_part[(size_t)2 * SZ_X];        // coil-half partials

__device__ __forceinline__ int brev9(int i) { return (int)(__brev((unsigned)i) >> 23); }
__device__ __forceinline__ int phys(int e)  { return e + (e >> 3); }
__device__ __forceinline__ int phys2(int e) { return e + (e >> 4); }
__device__ __forceinline__ float2 cmul(float2 a, float2 w) {
    return make_float2(a.x * w.x - a.y * w.y, a.x * w.y + a.y * w.x);
}

// 2-warp named barrier (used by the validated 8pt kernels k_f1 / k_i2)
#define BAR64(id) asm volatile("bar.sync %0, 64;" :: "r"(id) : "memory")

// ---------------------------------------------------------------------------
// Radix-8 register phase (R12/R14-validated; used by k_f1 and k_i2).
// ---------------------------------------------------------------------------
template<int P, bool DIF>
__device__ __forceinline__ void reg_fft_phase(float2* a, int lane,
                                              const float2* tw, float isign) {
    constexpr int str = (P == 0) ? 1 : ((P == 1) ? 8 : 64);
    int base;
    if (P == 0)      base = lane << 3;
    else if (P == 1) base = ((lane >> 3) << 6) | (lane & 7);
    else             base = lane;
    int b_lo = base & (str - 1);

    float2 r[8];
    #pragma unroll
    for (int m = 0; m < 8; m++) r[m] = a[phys(base + m * str)];

    #pragma unroll
    for (int ss = 0; ss < 3; ss++) {
        const int sub = DIF ? (2 - ss) : ss;
        const int s = 3 * P + sub + 1;
        const int half_m = 1 << sub;
        #pragma unroll
        for (int q = 0; q < 4; q++) {
            int jm = q & (half_m - 1);
            int m0 = ((q ^ jm) << 1) + jm;
            int m1 = m0 + half_m;
            float2 A = r[m0], B = r[m1];
            if (P == 0 && sub == 0) {
                r[m0] = make_float2(A.x + B.x, A.y + B.y);
                r[m1] = make_float2(A.x - B.x, A.y - B.y);
            } else {
                int j = jm * str + b_lo;
                float2 w = tw[(j << (9 - s)) & 255];
                w.y *= isign;
                if (!DIF) {
                    float2 t = cmul(B, w);
                    r[m0] = make_float2(A.x + t.x, A.y + t.y);
                    r[m1] = make_float2(A.x - t.x, A.y - t.y);
                } else {
                    float2 d = make_float2(A.x - B.x, A.y - B.y);
                    r[m0] = make_float2(A.x + B.x, A.y + B.y);
                    r[m1] = cmul(d, w);
                }
            }
        }
    }
    #pragma unroll
    for (int m = 0; m < 8; m++) a[phys(base + m * str)] = r[m];
}

// ---------------------------------------------------------------------------
// k_tr: tiled transpose kernels[ba][h][w] -> g_kT[ba][w][h]   (R14-exact)
// ---------------------------------------------------------------------------
__global__ void __launch_bounds__(256)
k_tr(const float* __restrict__ kr, const float* __restrict__ ki) {
    __shared__ float2 t[32][33];
    int ba = blockIdx.z;
    int tx = threadIdx.x & 31, ty = threadIdx.x >> 5;
    int h0 = blockIdx.y * 32, w0 = blockIdx.x * 32;
    #pragma unroll
    for (int k = 0; k < 4; k++) {
        size_t o = (size_t)ba * NPIX + (size_t)(h0 + ty + k * 8) * HP + w0 + tx;
        t[ty + k * 8][tx] = make_float2(kr[o], ki[o]);
    }
    __syncthreads();
    #pragma unroll
    for (int k = 0; k < 4; k++) {
        g_kT[(size_t)ba * NPIX + (size_t)(w0 + ty + k * 8) * HP + h0 + tx] = t[tx][ty + k * 8];
    }
}

// ---------------------------------------------------------------------------
// k_f1: row FFTs of padded x*mps. (R14-exact)
// ---------------------------------------------------------------------------
__global__ void __launch_bounds__(256)
k_f1(const float* __restrict__ xr, const float* __restrict__ xi,
     const float* __restrict__ mr, const float* __restrict__ mi) {
    __shared__ float2 d[4][PH];
    __shared__ float2 tw[256];
    int tid = threadIdx.x;
    { float sv, cv; sincospif(-(float)tid / 256.0f, &sv, &cv); tw[tid] = make_float2(cv, sv); }

    int img = blockIdx.x >> 6;
    int row0 = (blockIdx.x & 63) * 4;
    int a = img % AA, nc = img / AA, c = nc % CC, n = nc / CC;
    int row = tid >> 6, lane = tid & 63;
    int bar = row + 1;

    #pragma unroll
    for (int k = lane; k < PH; k += 64) d[row][k] = make_float2(0.f, 0.f);
    BAR64(bar);
    size_t xoff = ((size_t)(n * AA + a) * HH + row0 + row) * HH;
    size_t moff = ((size_t)c * HH + row0 + row) * HH;
    #pragma unroll
    for (int k = 0; k < 4; k++) {
        int iw = lane + k * 64;
        float ar = xr[xoff + iw], ai = xi[xoff + iw];
        float br = mr[moff + iw], bi = mi[moff + iw];
        d[row][phys(brev9(128 + iw))] = make_float2(ar * br - ai * bi, ar * bi + ai * br);
    }
    __syncthreads();

    reg_fft_phase<0,false>(d[row], lane, tw, 1.f); BAR64(bar);
    reg_fft_phase<1,false>(d[row], lane, tw, 1.f); BAR64(bar);
    reg_fft_phase<2,false>(d[row], lane, tw, 1.f);
    __syncthreads();

    for (int w = tid; w < 512; w += 256) {
        float2 v0 = d[0][phys(w)], v1 = d[1][phys(w)];
        float2 v2 = d[2][phys(w)], v3 = d[3][phys(w)];
        float4* p = (float4*)&g_bufA[((size_t)img * HP + w) * HH + row0];
        p[0] = make_float4(v0.x, v0.y, v1.x, v1.y);
        p[1] = make_float4(v2.x, v2.y, v3.x, v3.y);
    }
}

// ---------------------------------------------------------------------------
// k_fused (NEW): warp-synchronous 16pt/thread column FFT + mix + inverse.
// One warp = one (array, col) 512-pt FFT. 10 warps = 5 arrays x 2 cols.
// Stages: [1-4 regs] smem [5-8 regs] smem [9 fused w/ natural write].
// Bit-reversed zero-padded load and cropped store done directly in registers.
// ---------------------------------------------------------------------------
__global__ void __launch_bounds__(320, 3)
k_fused() {
    __shared__ float2 d[10][PH2];
    __shared__ float2 tw[256];
    int tid = threadIdx.x;
    if (tid < 256) { float sv, cv; sincospif(-(float)tid / 256.0f, &sv, &cv); tw[tid] = make_float2(cv, sv); }

    int bid = blockIdx.x;
    int nc = bid % (NN * CC);              // nc-major: consecutive bids share w-tile? no: share tile across nc (kT L2 reuse)
    int w0 = (bid / (NN * CC)) * 2;

    int wid = tid >> 5, lane = tid & 31;
    int arr = wid >> 1, col = wid & 1;
    int img = nc * AA + arr;
    int rev5L = (int)(__brev((unsigned)lane) >> 27);
    constexpr int rev4t[16] = {0,8,4,12,2,10,6,14,1,9,5,13,3,11,7,15};
    float2* D = d[wid];
    const float2* in = &g_bufA[((size_t)img * HP + w0 + col) * HH];

    // direct bit-reversed zero-padded load into registers
    // storage idx q = 16*lane + i  ->  n = brev9(q) = 32*rev4(i) + rev5(lane)
    float2 r[16];
    #pragma unroll
    for (int i = 0; i < 16; i++) {
        int rv = rev4t[i];
        r[i] = (rv >= 4 && rv < 12) ? in[((rv - 4) << 5) + rev5L]
                                    : make_float2(0.f, 0.f);
    }
    __syncthreads();   // tw table ready for all warps

    // ---- forward stages 1-4 in registers ----
    #pragma unroll
    for (int i = 0; i < 16; i += 2) {      // stage 1: w == 1
        float2 A = r[i], B = r[i + 1];
        r[i]     = make_float2(A.x + B.x, A.y + B.y);
        r[i + 1] = make_float2(A.x - B.x, A.y - B.y);
    }
    #pragma unroll
    for (int s = 2; s <= 4; s++) {
        int half = 1 << (s - 1);
        #pragma unroll
        for (int i = 0; i < 16; i++) if (!(i & half)) {
            float2 w = tw[((i & (half - 1)) << (9 - s)) & 255];
            float2 t = cmul(r[i + half], w);
            float2 A = r[i];
            r[i]        = make_float2(A.x + t.x, A.y + t.y);
            r[i + half] = make_float2(A.x - t.x, A.y - t.y);
        }
    }
    #pragma unroll
    for (int i = 0; i < 16; i++) D[phys2(16 * lane + i)] = r[i];
    __syncwarp();

    // ---- forward stages 5-8 in registers ----
    int g = lane >> 4, u = lane & 15;
    int bbase = 256 * g + u;
    #pragma unroll
    for (int m = 0; m < 16; m++) r[m] = D[phys2(bbase + 16 * m)];
    #pragma unroll
    for (int s = 5; s <= 8; s++) {
        int hm = 1 << (s - 5);
        #pragma unroll
        for (int m = 0; m < 16; m++) if (!(m & hm)) {
            float2 w = tw[((u + 16 * (m & (hm - 1))) << (9 - s)) & 255];
            float2 t = cmul(r[m + hm], w);
            float2 A = r[m];
            r[m]      = make_float2(A.x + t.x, A.y + t.y);
            r[m + hm] = make_float2(A.x - t.x, A.y - t.y);
        }
    }
    #pragma unroll
    for (int m = 0; m < 16; m++) D[phys2(bbase + 16 * m)] = r[m];
    __syncwarp();

    // ---- forward stage 9, write natural order ----
    #pragma unroll
    for (int jj = 0; jj < 8; jj++) {
        int p = 8 * lane + jj;
        float2 A = D[phys2(p)], B = D[phys2(p + 256)];
        float2 t = cmul(B, tw[p]);
        D[phys2(p)]       = make_float2(A.x + t.x, A.y + t.y);
        D[phys2(p + 256)] = make_float2(A.x - t.x, A.y - t.y);
    }
    __syncthreads();

    // ---- mix: G[b](h,w) = sum_a K[b][a](h,w) * F[a](h,w) ----
    for (int i = tid; i < 2 * 512; i += 320) {
        int mcol = i >> 9, t = i & 511;
        size_t kbase = (size_t)(w0 + mcol) * HP + t;
        float2 F[5], G[5];
        #pragma unroll
        for (int a2 = 0; a2 < 5; a2++) F[a2] = d[a2 * 2 + mcol][phys2(t)];
        #pragma unroll
        for (int b = 0; b < 5; b++) {
            float2 acc = make_float2(0.f, 0.f);
            #pragma unroll
            for (int a2 = 0; a2 < 5; a2++) {
                float2 K = g_kT[(size_t)(b * 5 + a2) * NPIX + kbase];
                acc.x += K.x * F[a2].x - K.y * F[a2].y;
                acc.y += K.x * F[a2].y + K.y * F[a2].x;
            }
            G[b] = acc;
        }
        #pragma unroll
        for (int b = 0; b < 5; b++) d[b * 2 + mcol][phys2(t)] = G[b];
    }
    __syncthreads();

    // ---- inverse stage 9 (conj twiddle, DIF) ----
    #pragma unroll
    for (int jj = 0; jj < 8; jj++) {
        int p = 8 * lane + jj;
        float2 A = D[phys2(p)], B = D[phys2(p + 256)];
        float2 w = tw[p]; w.y = -w.y;
        float2 dd = make_float2(A.x - B.x, A.y - B.y);
        D[phys2(p)]       = make_float2(A.x + B.x, A.y + B.y);
        D[phys2(p + 256)] = cmul(dd, w);
    }
    __syncwarp();

    // ---- inverse stages 8..5 ----
    #pragma unroll
    for (int m = 0; m < 16; m++) r[m] = D[phys2(bbase + 16 * m)];
    #pragma unroll
    for (int s = 8; s >= 5; s--) {
        int hm = 1 << (s - 5);
        #pragma unroll
        for (int m = 0; m < 16; m++) if (!(m & hm)) {
            float2 w = tw[((u + 16 * (m & (hm - 1))) << (9 - s)) & 255]; w.y = -w.y;
            float2 A = r[m], B = r[m + hm];
            float2 dd = make_float2(A.x - B.x, A.y - B.y);
            r[m]      = make_float2(A.x + B.x, A.y + B.y);
            r[m + hm] = cmul(dd, w);
        }
    }
    #pragma unroll
    for (int m = 0; m < 16; m++) D[phys2(bbase + 16 * m)] = r[m];
    __syncwarp();

    // ---- inverse stages 4..1 + direct cropped store ----
    #pragma unroll
    for (int i = 0; i < 16; i++) r[i] = D[phys2(16 * lane + i)];
    #pragma unroll
    for (int s = 4; s >= 2; s--) {
        int half = 1 << (s - 1);
        #pragma unroll
        for (int i = 0; i < 16; i++) if (!(i & half)) {
            float2 w = tw[((i & (half - 1)) << (9 - s)) & 255]; w.y = -w.y;
            float2 A = r[i], B = r[i + half];
            float2 dd = make_float2(A.x - B.x, A.y - B.y);
            r[i]        = make_float2(A.x + B.x, A.y + B.y);
            r[i + half] = cmul(dd, w);
        }
    }
    #pragma unroll
    for (int i = 0; i < 16; i += 2) {      // stage 1: w == 1
        float2 A = r[i], B = r[i + 1];
        r[i]     = make_float2(A.x + B.x, A.y + B.y);
        r[i + 1] = make_float2(A.x - B.x, A.y - B.y);
    }
    const float sc = 1.0f / 512.0f;
    float2* outp = &g_bufA[((size_t)img * HP + w0 + col) * HH];
    #pragma unroll
    for (int i = 0; i < 16; i++) {
        int rv = rev4t[i];
        if (rv >= 4 && rv < 12)
            outp[((rv - 4) << 5) + rev5L] = make_float2(r[i].x * sc, r[i].y * sc);
    }
}

// ---------------------------------------------------------------------------
// k_i2: inverse row FFTs + crop + conj(mps) over half the coils. (R14-exact)
// ---------------------------------------------------------------------------
__global__ void __launch_bounds__(256)
k_i2(const float* __restrict__ mr, const float* __restrict__ mi) {
    __shared__ float2 d[4][PH];
    __shared__ float2 tw[256];
    int tid = threadIdx.x;
    { float sv, cv; sincospif(-(float)tid / 256.0f, &sv, &cv); tw[tid] = make_float2(cv, sv); }

    int bid = blockIdx.x;
    int row0 = (bid & 63) * 4;
    int cgnb = bid >> 6;
    int cg = cgnb & 1;
    int nb = cgnb >> 1;
    int b = nb % AA;
    int n = nb / AA;

    int row = tid >> 6, lane = tid & 63;
    int bar = row + 1;

    float2 acc[4];
    #pragma unroll
    for (int k = 0; k < 4; k++) acc[k] = make_float2(0.f, 0.f);

    for (int ci = 0; ci < 6; ci++) {
        int c = cg * 6 + ci;
        int img = (n * CC + c) * AA + b;
        __syncthreads();
        for (int w = tid; w < 512; w += 256) {
            const float4* p = (const float4*)&g_bufA[((size_t)img * HP + w) * HH + row0];
            float4 q0 = p[0], q1 = p[1];
            d[0][phys(w)] = make_float2(q0.x, q0.y);
            d[1][phys(w)] = make_float2(q0.z, q0.w);
            d[2][phys(w)] = make_float2(q1.x, q1.y);
            d[3][phys(w)] = make_float2(q1.z, q1.w);
        }
        __syncthreads();

        reg_fft_phase<2,true>(d[row], lane, tw, -1.f); BAR64(bar);
        reg_fft_phase<1,true>(d[row], lane, tw, -1.f); BAR64(bar);
        reg_fft_phase<0,true>(d[row], lane, tw, -1.f); BAR64(bar);

        size_t moff = ((size_t)c * HH + row0 + row) * HH;
        #pragma unroll
        for (int k = 0; k < 4; k++) {
            int cw = lane + k * 64;
            float2 v = d[row][phys(brev9(128 + cw))];
            float m_r = mr[moff + cw], m_i = mi[moff + cw];
            acc[k].x += v.x * m_r + v.y * m_i;
            acc[k].y += v.y * m_r - v.x * m_i;
        }
    }

    size_t obase = ((size_t)(n * AA + b) * HH + row0 + row) * HH;
    #pragma unroll
    for (int k = 0; k < 4; k++) {
        g_part[(size_t)cg * SZ_X + obase + lane + k * 64] = acc[k];
    }
}

// ---------------------------------------------------------------------------
// k_comb: add coil-half partials, scale, planar output. (R14-exact)
// ---------------------------------------------------------------------------
__global__ void __launch_bounds__(256)
k_comb(float* __restrict__ out, long out_floats) {
    size_t o = (size_t)blockIdx.x * 256 + threadIdx.x;
    float2 v0 = g_part[o], v1 = g_part[(size_t)SZ_X + o];
    const float sc = 4.0f / 512.0f;
    float re = (v0.x + v1.x) * sc;
    float im = (v0.y + v1.y) * sc;
    if ((long)o < out_floats) out[o] = re;
    if ((long)(SZ_X + o) < out_floats) out[SZ_X + o] = im;
}

// ---------------------------------------------------------------------------
// Input resolver (R7..R14-validated)
// ---------------------------------------------------------------------------
static void pick(void* const* d_in, const int* in_sizes, int n_in, long S,
                 int pos_split, const float** re, const float** im) {
    int idx[2] = {-1, -1};
    int cnt = 0;
    for (int i = 0; i < n_in; i++) {
        long v = (long)in_sizes[i];
        if (v == S || v == 2 * S || v == 4 * S || v == 8 * S) {
            if (cnt < 2) idx[cnt] = i;
            cnt++;
        }
    }
    if (cnt >= 2) {
        *re = (const float*)d_in[idx[0]];
        *im = (const float*)d_in[idx[1]];
    } else if (cnt == 1) {
        *re = (const float*)d_in[idx[0]];
        *im = *re + 1;
    } else {
        int p0 = (pos_split < n_in) ? pos_split : 0;
        int p1 = (pos_split + 1 < n_in) ? pos_split + 1 : p0;
        *re = (const float*)d_in[p0];
        *im = (const float*)d_in[p1];
    }
}

extern "C" void kernel_launch(void* const* d_in, const int* in_sizes, int n_in,
                              void* d_out, int out_size) {
    const float *xr, *xi, *mr, *mi, *kr, *ki;
    pick(d_in, in_sizes, n_in, SZ_X, 0, &xr, &xi);
    pick(d_in, in_sizes, n_in, SZ_M, 2, &mr, &mi);
    pick(d_in, in_sizes, n_in, SZ_K, 4, &kr, &ki);
    float* out = (float*)d_out;

    dim3 trg(16, 16, 25);
    k_tr<<<trg, 256>>>(kr, ki);
    k_f1<<<NIMG * 64, 256>>>(xr, xi, mr, mi);
    k_fused<<<(NN * CC) * (HP / 2), 320>>>();
    k_i2<<<NN * AA * 64 * 2, 256>>>(mr, mi);
    k_comb<<<(int)(SZ_X / 256), 256>>>(out, (long)out_size);
}

// round 16
// speedup vs baseline: 1.0961x; 1.0467x over previous
#include <cuda_runtime.h>
#include <cstdint>

#define NN 2
#define CC 12
#define AA 5
#define HH 256
#define HP 512
#define NIMG (NN*CC*AA)         // 120
#define NPIX (HP*HP)            // 262144
#define PH 576                  // padded smem line for 8pt kernels
#define PH2 544                 // padded smem line for 16pt kernel

#define SZ_X ((long)NN*AA*HH*HH)   // 655360
#define SZ_M ((long)CC*HH*HH)      // 786432
#define SZ_K ((long)AA*AA*HP*HP)   // 6553600

// Scratch: 125.8 + 52.4 + 10.5 = 188.7MB (< ~190MB module limit from R1-R4)
__device__ __align__(128) float2 g_bufA[(size_t)NIMG * HP * HH];  // [img][w][r]
__device__ __align__(128) float2 g_kT[(size_t)25 * NPIX];         // [ba][w][h]
__device__ __align__(128) float2 g_part[(size_t)2 * SZ_X];        // coil-half partials

__device__ __forceinline__ int brev9(int i) { return (int)(__brev((unsigned)i) >> 23); }
__device__ __forceinline__ int phys(int e)  { return e + (e >> 3); }
__device__ __forceinline__ int phys2(int e) { return e + (e >> 4); }
__device__ __forceinline__ float2 cmul(float2 a, float2 w) {
    return make_float2(a.x * w.x - a.y * w.y, a.x * w.y + a.y * w.x);
}

#define BAR64(id) asm volatile("bar.sync %0, 64;" :: "r"(id) : "memory")

// ---------------------------------------------------------------------------
// Radix-8 register phase (R12/R14-validated; used by k_f1 and k_i2).
// ---------------------------------------------------------------------------
template<int P, bool DIF>
__device__ __forceinline__ void reg_fft_phase(float2* a, int lane,
                                              const float2* tw, float isign) {
    constexpr int str = (P == 0) ? 1 : ((P == 1) ? 8 : 64);
    int base;
    if (P == 0)      base = lane << 3;
    else if (P == 1) base = ((lane >> 3) << 6) | (lane & 7);
    else             base = lane;
    int b_lo = base & (str - 1);

    float2 r[8];
    #pragma unroll
    for (int m = 0; m < 8; m++) r[m] = a[phys(base + m * str)];

    #pragma unroll
    for (int ss = 0; ss < 3; ss++) {
        const int sub = DIF ? (2 - ss) : ss;
        const int s = 3 * P + sub + 1;
        const int half_m = 1 << sub;
        #pragma unroll
        for (int q = 0; q < 4; q++) {
            int jm = q & (half_m - 1);
            int m0 = ((q ^ jm) << 1) + jm;
            int m1 = m0 + half_m;
            float2 A = r[m0], B = r[m1];
            if (P == 0 && sub == 0) {
                r[m0] = make_float2(A.x + B.x, A.y + B.y);
                r[m1] = make_float2(A.x - B.x, A.y - B.y);
            } else {
                int j = jm * str + b_lo;
                float2 w = tw[(j << (9 - s)) & 255];
                w.y *= isign;
                if (!DIF) {
                    float2 t = cmul(B, w);
                    r[m0] = make_float2(A.x + t.x, A.y + t.y);
                    r[m1] = make_float2(A.x - t.x, A.y - t.y);
                } else {
                    float2 d = make_float2(A.x - B.x, A.y - B.y);
                    r[m0] = make_float2(A.x + B.x, A.y + B.y);
                    r[m1] = cmul(d, w);
                }
            }
        }
    }
    #pragma unroll
    for (int m = 0; m < 8; m++) a[phys(base + m * str)] = r[m];
}

// ---------------------------------------------------------------------------
// k_tr: tiled transpose kernels[ba][h][w] -> g_kT[ba][w][h]   (validated)
// ---------------------------------------------------------------------------
__global__ void __launch_bounds__(256)
k_tr(const float* __restrict__ kr, const float* __restrict__ ki) {
    __shared__ float2 t[32][33];
    int ba = blockIdx.z;
    int tx = threadIdx.x & 31, ty = threadIdx.x >> 5;
    int h0 = blockIdx.y * 32, w0 = blockIdx.x * 32;
    #pragma unroll
    for (int k = 0; k < 4; k++) {
        size_t o = (size_t)ba * NPIX + (size_t)(h0 + ty + k * 8) * HP + w0 + tx;
        t[ty + k * 8][tx] = make_float2(kr[o], ki[o]);
    }
    __syncthreads();
    #pragma unroll
    for (int k = 0; k < 4; k++) {
        g_kT[(size_t)ba * NPIX + (size_t)(w0 + ty + k * 8) * HP + h0 + tx] = t[tx][ty + k * 8];
    }
}

// ---------------------------------------------------------------------------
// k_f1: row FFTs of padded x*mps. Block = (img, 2 rows), 128 thr.
// More resident blocks (6/SM) -> more independent chains per scheduler.
// ---------------------------------------------------------------------------
__global__ void __launch_bounds__(128)
k_f1(const float* __restrict__ xr, const float* __restrict__ xi,
     const float* __restrict__ mr, const float* __restrict__ mi) {
    __shared__ float2 d[2][PH];
    __shared__ float2 tw[256];
    int tid = threadIdx.x;
    {
        float sv, cv;
        sincospif(-(float)tid / 256.0f, &sv, &cv); tw[tid] = make_float2(cv, sv);
        sincospif(-(float)(tid + 128) / 256.0f, &sv, &cv); tw[tid + 128] = make_float2(cv, sv);
    }

    int img = blockIdx.x >> 7;
    int row0 = (blockIdx.x & 127) * 2;
    int a = img % AA, nc = img / AA, c = nc % CC, n = nc / CC;
    int row = tid >> 6, lane = tid & 63;
    int bar = row + 1;

    #pragma unroll
    for (int k = lane; k < PH; k += 64) d[row][k] = make_float2(0.f, 0.f);
    BAR64(bar);
    size_t xoff = ((size_t)(n * AA + a) * HH + row0 + row) * HH;
    size_t moff = ((size_t)c * HH + row0 + row) * HH;
    #pragma unroll
    for (int k = 0; k < 4; k++) {
        int iw = lane + k * 64;
        float ar = xr[xoff + iw], ai = xi[xoff + iw];
        float br = mr[moff + iw], bi = mi[moff + iw];
        d[row][phys(brev9(128 + iw))] = make_float2(ar * br - ai * bi, ar * bi + ai * br);
    }
    __syncthreads();

    reg_fft_phase<0,false>(d[row], lane, tw, 1.f); BAR64(bar);
    reg_fft_phase<1,false>(d[row], lane, tw, 1.f); BAR64(bar);
    reg_fft_phase<2,false>(d[row], lane, tw, 1.f);
    __syncthreads();

    for (int w = tid; w < 512; w += 128) {
        float2 v0 = d[0][phys(w)], v1 = d[1][phys(w)];
        *(float4*)&g_bufA[((size_t)img * HP + w) * HH + row0] =
            make_float4(v0.x, v0.y, v1.x, v1.y);
    }
}

// ---------------------------------------------------------------------------
// k_fused: warp-synchronous 16pt/thread column FFT + mix + inverse.
// (320,2): no reg spills. Register-only pad/crop fold at load/store.
// ---------------------------------------------------------------------------
__global__ void __launch_bounds__(320, 2)
k_fused() {
    __shared__ float2 d[10][PH2];
    __shared__ float2 tw[256];
    int tid = threadIdx.x;
    if (tid < 256) { float sv, cv; sincospif(-(float)tid / 256.0f, &sv, &cv); tw[tid] = make_float2(cv, sv); }

    int bid = blockIdx.x;
    int nc = bid % (NN * CC);
    int w0 = (bid / (NN * CC)) * 2;

    int wid = tid >> 5, lane = tid & 31;
    int arr = wid >> 1, col = wid & 1;
    int img = nc * AA + arr;
    int rev5L = (int)(__brev((unsigned)lane) >> 27);
    float2* D = d[wid];
    const float2* in = &g_bufA[((size_t)img * HP + w0 + col) * HH];

    // load nonzero inputs and construct post-stage-1 registers directly:
    // storage q=16*lane+i -> n=32*rev4(i)+rev5(lane); nonzero iff rev4(i) in [4,12)
    float2 r[16];
    {
        float2 v1  = in[128 + rev5L];   // i=1,  rv=8
        float2 v2  = in[  0 + rev5L];   // i=2,  rv=4
        float2 v5  = in[192 + rev5L];   // i=5,  rv=10
        float2 v6  = in[ 64 + rev5L];   // i=6,  rv=6
        float2 v9  = in[160 + rev5L];   // i=9,  rv=9
        float2 v10 = in[ 32 + rev5L];   // i=10, rv=5
        float2 v13 = in[224 + rev5L];   // i=13, rv=11
        float2 v14 = in[ 96 + rev5L];   // i=14, rv=7
        r[0] = v1;  r[1] = make_float2(-v1.x, -v1.y);
        r[2] = v2;  r[3] = v2;
        r[4] = v5;  r[5] = make_float2(-v5.x, -v5.y);
        r[6] = v6;  r[7] = v6;
        r[8] = v9;  r[9] = make_float2(-v9.x, -v9.y);
        r[10] = v10; r[11] = v10;
        r[12] = v13; r[13] = make_float2(-v13.x, -v13.y);
        r[14] = v14; r[15] = v14;
    }
    __syncthreads();   // tw table ready

    // ---- forward stages 2-4 in registers ----
    #pragma unroll
    for (int s = 2; s <= 4; s++) {
        int half = 1 << (s - 1);
        #pragma unroll
        for (int i = 0; i < 16; i++) if (!(i & half)) {
            float2 w = tw[((i & (half - 1)) << (9 - s)) & 255];
            float2 t = cmul(r[i + half], w);
            float2 A = r[i];
            r[i]        = make_float2(A.x + t.x, A.y + t.y);
            r[i + half] = make_float2(A.x - t.x, A.y - t.y);
        }
    }
    #pragma unroll
    for (int i = 0; i < 16; i++) D[phys2(16 * lane + i)] = r[i];
    __syncwarp();

    // ---- forward stages 5-8 in registers ----
    int g = lane >> 4, u = lane & 15;
    int bbase = 256 * g + u;
    #pragma unroll
    for (int m = 0; m < 16; m++) r[m] = D[phys2(bbase + 16 * m)];
    #pragma unroll
    for (int s = 5; s <= 8; s++) {
        int hm = 1 << (s - 5);
        #pragma unroll
        for (int m = 0; m < 16; m++) if (!(m & hm)) {
            float2 w = tw[((u + 16 * (m & (hm - 1))) << (9 - s)) & 255];
            float2 t = cmul(r[m + hm], w);
            float2 A = r[m];
            r[m]      = make_float2(A.x + t.x, A.y + t.y);
            r[m + hm] = make_float2(A.x - t.x, A.y - t.y);
        }
    }
    #pragma unroll
    for (int m = 0; m < 16; m++) D[phys2(bbase + 16 * m)] = r[m];
    __syncwarp();

    // ---- forward stage 9, natural order in smem ----
    #pragma unroll
    for (int jj = 0; jj < 8; jj++) {
        int p = 8 * lane + jj;
        float2 A = D[phys2(p)], B = D[phys2(p + 256)];
        float2 t = cmul(B, tw[p]);
        D[phys2(p)]       = make_float2(A.x + t.x, A.y + t.y);
        D[phys2(p + 256)] = make_float2(A.x - t.x, A.y - t.y);
    }
    __syncthreads();

    // ---- mix ----
    for (int i = tid; i < 2 * 512; i += 320) {
        int mcol = i >> 9, t = i & 511;
        size_t kbase = (size_t)(w0 + mcol) * HP + t;
        float2 F[5], G[5];
        #pragma unroll
        for (int a2 = 0; a2 < 5; a2++) F[a2] = d[a2 * 2 + mcol][phys2(t)];
        #pragma unroll
        for (int b = 0; b < 5; b++) {
            float2 acc = make_float2(0.f, 0.f);
            #pragma unroll
            for (int a2 = 0; a2 < 5; a2++) {
                float2 K = g_kT[(size_t)(b * 5 + a2) * NPIX + kbase];
                acc.x += K.x * F[a2].x - K.y * F[a2].y;
                acc.y += K.x * F[a2].y + K.y * F[a2].x;
            }
            G[b] = acc;
        }
        #pragma unroll
        for (int b = 0; b < 5; b++) d[b * 2 + mcol][phys2(t)] = G[b];
    }
    __syncthreads();

    // ---- inverse stage 9 ----
    #pragma unroll
    for (int jj = 0; jj < 8; jj++) {
        int p = 8 * lane + jj;
        float2 A = D[phys2(p)], B = D[phys2(p + 256)];
        float2 w = tw[p]; w.y = -w.y;
        float2 dd = make_float2(A.x - B.x, A.y - B.y);
        D[phys2(p)]       = make_float2(A.x + B.x, A.y + B.y);
        D[phys2(p + 256)] = cmul(dd, w);
    }
    __syncwarp();

    // ---- inverse stages 8..5 ----
    #pragma unroll
    for (int m = 0; m < 16; m++) r[m] = D[phys2(bbase + 16 * m)];
    #pragma unroll
    for (int s = 8; s >= 5; s--) {
        int hm = 1 << (s - 5);
        #pragma unroll
        for (int m = 0; m < 16; m++) if (!(m & hm)) {
            float2 w = tw[((u + 16 * (m & (hm - 1))) << (9 - s)) & 255]; w.y = -w.y;
            float2 A = r[m], B = r[m + hm];
            float2 dd = make_float2(A.x - B.x, A.y - B.y);
            r[m]      = make_float2(A.x + B.x, A.y + B.y);
            r[m + hm] = cmul(dd, w);
        }
    }
    #pragma unroll
    for (int m = 0; m < 16; m++) D[phys2(bbase + 16 * m)] = r[m];
    __syncwarp();

    // ---- inverse stages 4..2, then folded stage-1 + cropped store ----
    #pragma unroll
    for (int i = 0; i < 16; i++) r[i] = D[phys2(16 * lane + i)];
    #pragma unroll
    for (int s = 4; s >= 2; s--) {
        int half = 1 << (s - 1);
        #pragma unroll
        for (int i = 0; i < 16; i++) if (!(i & half)) {
            float2 w = tw[((i & (half - 1)) << (9 - s)) & 255]; w.y = -w.y;
            float2 A = r[i], B = r[i + half];
            float2 dd = make_float2(A.x - B.x, A.y - B.y);
            r[i]        = make_float2(A.x + B.x, A.y + B.y);
            r[i + half] = cmul(dd, w);
        }
    }
    // stage-1 (w==1) + crop: keep only outputs with rev4(i) in [4,12)
    const float sc = 1.0f / 512.0f;
    float2* outp = &g_bufA[((size_t)img * HP + w0 + col) * HH];
    outp[128 + rev5L] = make_float2((r[0].x - r[1].x) * sc,  (r[0].y - r[1].y) * sc);   // i=1
    outp[  0 + rev5L] = make_float2((r[2].x + r[3].x) * sc,  (r[2].y + r[3].y) * sc);   // i=2
    outp[192 + rev5L] = make_float2((r[4].x - r[5].x) * sc,  (r[4].y - r[5].y) * sc);   // i=5
    outp[ 64 + rev5L] = make_float2((r[6].x + r[7].x) * sc,  (r[6].y + r[7].y) * sc);   // i=6
    outp[160 + rev5L] = make_float2((r[8].x - r[9].x) * sc,  (r[8].y - r[9].y) * sc);   // i=9
    outp[ 32 + rev5L] = make_float2((r[10].x + r[11].x) * sc,(r[10].y + r[11].y) * sc); // i=10
    outp[224 + rev5L] = make_float2((r[12].x - r[13].x) * sc,(r[12].y - r[13].y) * sc); // i=13
    outp[ 96 + rev5L] = make_float2((r[14].x + r[15].x) * sc,(r[14].y + r[15].y) * sc); // i=14
}

// ---------------------------------------------------------------------------
// k_i2: inverse row FFTs + crop + conj(mps) over half the coils.
// Block = (cg, n, b, 2 rows), 128 thr -> 6 resident blocks/SM.
// ---------------------------------------------------------------------------
__global__ void __launch_bounds__(128)
k_i2(const float* __restrict__ mr, const float* __restrict__ mi) {
    __shared__ float2 d[2][PH];
    __shared__ float2 tw[256];
    int tid = threadIdx.x;
    {
        float sv, cv;
        sincospif(-(float)tid / 256.0f, &sv, &cv); tw[tid] = make_float2(cv, sv);
        sincospif(-(float)(tid + 128) / 256.0f, &sv, &cv); tw[tid + 128] = make_float2(cv, sv);
    }

    int bid = blockIdx.x;
    int row0 = (bid & 127) * 2;
    int cgnb = bid >> 7;
    int cg = cgnb & 1;
    int nb = cgnb >> 1;
    int b = nb % AA;
    int n = nb / AA;

    int row = tid >> 6, lane = tid & 63;
    int bar = row + 1;

    float2 acc[4];
    #pragma unroll
    for (int k = 0; k < 4; k++) acc[k] = make_float2(0.f, 0.f);

    for (int ci = 0; ci < 6; ci++) {
        int c = cg * 6 + ci;
        int img = (n * CC + c) * AA + b;
        __syncthreads();   // prior accum reads done (also tw on first iter)
        for (int w = tid; w < 512; w += 128) {
            float4 q = *(const float4*)&g_bufA[((size_t)img * HP + w) * HH + row0];
            d[0][phys(w)] = make_float2(q.x, q.y);
            d[1][phys(w)] = make_float2(q.z, q.w);
        }
        __syncthreads();

        reg_fft_phase<2,true>(d[row], lane, tw, -1.f); BAR64(bar);
        reg_fft_phase<1,true>(d[row], lane, tw, -1.f); BAR64(bar);
        reg_fft_phase<0,true>(d[row], lane, tw, -1.f); BAR64(bar);

        size_t moff = ((size_t)c * HH + row0 + row) * HH;
        #pragma unroll
        for (int k = 0; k < 4; k++) {
            int cw = lane + k * 64;
            float2 v = d[row][phys(brev9(128 + cw))];
            float m_r = mr[moff + cw], m_i = mi[moff + cw];
            acc[k].x += v.x * m_r + v.y * m_i;   // v * conj(m)
            acc[k].y += v.y * m_r - v.x * m_i;
        }
    }

    size_t obase = ((size_t)(n * AA + b) * HH + row0 + row) * HH;
    #pragma unroll
    for (int k = 0; k < 4; k++) {
        g_part[(size_t)cg * SZ_X + obase + lane + k * 64] = acc[k];
    }
}

// ---------------------------------------------------------------------------
// k_comb: add coil-half partials, scale, planar output. (validated)
// ---------------------------------------------------------------------------
__global__ void __launch_bounds__(256)
k_comb(float* __restrict__ out, long out_floats) {
    size_t o = (size_t)blockIdx.x * 256 + threadIdx.x;
    float2 v0 = g_part[o], v1 = g_part[(size_t)SZ_X + o];
    const float sc = 4.0f / 512.0f;
    float re = (v0.x + v1.x) * sc;
    float im = (v0.y + v1.y) * sc;
    if ((long)o < out_floats) out[o] = re;
    if ((long)(SZ_X + o) < out_floats) out[SZ_X + o] = im;
}

// ---------------------------------------------------------------------------
// Input resolver (R7..R15-validated)
// ---------------------------------------------------------------------------
static void pick(void* const* d_in, const int* in_sizes, int n_in, long S,
                 int pos_split, const float** re, const float** im) {
    int idx[2] = {-1, -1};
    int cnt = 0;
    for (int i = 0; i < n_in; i++) {
        long v = (long)in_sizes[i];
        if (v == S || v == 2 * S || v == 4 * S || v == 8 * S) {
            if (cnt < 2) idx[cnt] = i;
            cnt++;
        }
    }
    if (cnt >= 2) {
        *re = (const float*)d_in[idx[0]];
        *im = (const float*)d_in[idx[1]];
    } else if (cnt == 1) {
        *re = (const float*)d_in[idx[0]];
        *im = *re + 1;
    } else {
        int p0 = (pos_split < n_in) ? pos_split : 0;
        int p1 = (pos_split + 1 < n_in) ? pos_split + 1 : p0;
        *re = (const float*)d_in[p0];
        *im = (const float*)d_in[p1];
    }
}

extern "C" void kernel_launch(void* const* d_in, const int* in_sizes, int n_in,
                              void* d_out, int out_size) {
    const float *xr, *xi, *mr, *mi, *kr, *ki;
    pick(d_in, in_sizes, n_in, SZ_X, 0, &xr, &xi);
    pick(d_in, in_sizes, n_in, SZ_M, 2, &mr, &mi);
    pick(d_in, in_sizes, n_in, SZ_K, 4, &kr, &ki);
    float* out = (float*)d_out;

    dim3 trg(16, 16, 25);
    k_tr<<<trg, 256>>>(kr, ki);
    k_f1<<<NIMG * 128, 128>>>(xr, xi, mr, mi);
    k_fused<<<(NN * CC) * (HP / 2), 320>>>();
    k_i2<<<NN * AA * 128 * 2, 128>>>(mr, mi);
    k_comb<<<(int)(SZ_X / 256), 256>>>(out, (long)out_size);
}

// round 17
// speedup vs baseline: 1.2212x; 1.1141x over previous
#include <cuda_runtime.h>
#include <cstdint>

#define NN 2
#define CC 12
#define AA 5
#define HH 256
#define HP 512
#define NIMG (NN*CC*AA)         // 120
#define NPIX (HP*HP)            // 262144
#define PH 576                  // padded smem line for 8pt kernels
#define PH2 544                 // padded smem line for 16pt kernel

#define SZ_X ((long)NN*AA*HH*HH)   // 655360
#define SZ_M ((long)CC*HH*HH)      // 786432
#define SZ_K ((long)AA*AA*HP*HP)   // 6553600

// Scratch: 125.8 + 52.4 + 10.5 = 188.7MB (< ~190MB module limit from R1-R4)
__device__ __align__(128) float2 g_bufA[(size_t)NIMG * HP * HH];  // [img][w][r]
__device__ __align__(128) float2 g_kT[(size_t)25 * NPIX];         // [ba][w][h]
__device__ __align__(128) float2 g_part[(size_t)2 * SZ_X];        // coil-half partials

__device__ __forceinline__ int brev9(int i) { return (int)(__brev((unsigned)i) >> 23); }
__device__ __forceinline__ int phys(int e)  { return e + (e >> 3); }
__device__ __forceinline__ int phys2(int e) { return e + (e >> 4); }
__device__ __forceinline__ float2 cmul(float2 a, float2 w) {
    return make_float2(a.x * w.x - a.y * w.y, a.x * w.y + a.y * w.x);
}

#define BAR64(id) asm volatile("bar.sync %0, 64;" :: "r"(id) : "memory")

// ---------------------------------------------------------------------------
// Radix-8 register phase (R12/R14-validated; used by k_f1 and k_i2).
// ---------------------------------------------------------------------------
template<int P, bool DIF>
__device__ __forceinline__ void reg_fft_phase(float2* a, int lane,
                                              const float2* tw, float isign) {
    constexpr int str = (P == 0) ? 1 : ((P == 1) ? 8 : 64);
    int base;
    if (P == 0)      base = lane << 3;
    else if (P == 1) base = ((lane >> 3) << 6) | (lane & 7);
    else             base = lane;
    int b_lo = base & (str - 1);

    float2 r[8];
    #pragma unroll
    for (int m = 0; m < 8; m++) r[m] = a[phys(base + m * str)];

    #pragma unroll
    for (int ss = 0; ss < 3; ss++) {
        const int sub = DIF ? (2 - ss) : ss;
        const int s = 3 * P + sub + 1;
        const int half_m = 1 << sub;
        #pragma unroll
        for (int q = 0; q < 4; q++) {
            int jm = q & (half_m - 1);
            int m0 = ((q ^ jm) << 1) + jm;
            int m1 = m0 + half_m;
            float2 A = r[m0], B = r[m1];
            if (P == 0 && sub == 0) {
                r[m0] = make_float2(A.x + B.x, A.y + B.y);
                r[m1] = make_float2(A.x - B.x, A.y - B.y);
            } else {
                int j = jm * str + b_lo;
                float2 w = tw[(j << (9 - s)) & 255];
                w.y *= isign;
                if (!DIF) {
                    float2 t = cmul(B, w);
                    r[m0] = make_float2(A.x + t.x, A.y + t.y);
                    r[m1] = make_float2(A.x - t.x, A.y - t.y);
                } else {
                    float2 d = make_float2(A.x - B.x, A.y - B.y);
                    r[m0] = make_float2(A.x + B.x, A.y + B.y);
                    r[m1] = cmul(d, w);
                }
            }
        }
    }
    #pragma unroll
    for (int m = 0; m < 8; m++) a[phys(base + m * str)] = r[m];
}

// ---------------------------------------------------------------------------
// k_tr: tiled transpose kernels[ba][h][w] -> g_kT[ba][w][h]   (validated)
// ---------------------------------------------------------------------------
__global__ void __launch_bounds__(256)
k_tr(const float* __restrict__ kr, const float* __restrict__ ki) {
    __shared__ float2 t[32][33];
    int ba = blockIdx.z;
    int tx = threadIdx.x & 31, ty = threadIdx.x >> 5;
    int h0 = blockIdx.y * 32, w0 = blockIdx.x * 32;
    #pragma unroll
    for (int k = 0; k < 4; k++) {
        size_t o = (size_t)ba * NPIX + (size_t)(h0 + ty + k * 8) * HP + w0 + tx;
        t[ty + k * 8][tx] = make_float2(kr[o], ki[o]);
    }
    __syncthreads();
    #pragma unroll
    for (int k = 0; k < 4; k++) {
        g_kT[(size_t)ba * NPIX + (size_t)(w0 + ty + k * 8) * HP + h0 + tx] = t[tx][ty + k * 8];
    }
}

// ---------------------------------------------------------------------------
// k_f1: row FFTs of padded x*mps. Block = (img, 4 rows), 256 thr. (R14-exact)
// ---------------------------------------------------------------------------
__global__ void __launch_bounds__(256)
k_f1(const float* __restrict__ xr, const float* __restrict__ xi,
     const float* __restrict__ mr, const float* __restrict__ mi) {
    __shared__ float2 d[4][PH];
    __shared__ float2 tw[256];
    int tid = threadIdx.x;
    { float sv, cv; sincospif(-(float)tid / 256.0f, &sv, &cv); tw[tid] = make_float2(cv, sv); }

    int img = blockIdx.x >> 6;
    int row0 = (blockIdx.x & 63) * 4;
    int a = img % AA, nc = img / AA, c = nc % CC, n = nc / CC;
    int row = tid >> 6, lane = tid & 63;
    int bar = row + 1;

    #pragma unroll
    for (int k = lane; k < PH; k += 64) d[row][k] = make_float2(0.f, 0.f);
    BAR64(bar);
    size_t xoff = ((size_t)(n * AA + a) * HH + row0 + row) * HH;
    size_t moff = ((size_t)c * HH + row0 + row) * HH;
    #pragma unroll
    for (int k = 0; k < 4; k++) {
        int iw = lane + k * 64;
        float ar = xr[xoff + iw], ai = xi[xoff + iw];
        float br = mr[moff + iw], bi = mi[moff + iw];
        d[row][phys(brev9(128 + iw))] = make_float2(ar * br - ai * bi, ar * bi + ai * br);
    }
    __syncthreads();

    reg_fft_phase<0,false>(d[row], lane, tw, 1.f); BAR64(bar);
    reg_fft_phase<1,false>(d[row], lane, tw, 1.f); BAR64(bar);
    reg_fft_phase<2,false>(d[row], lane, tw, 1.f);
    __syncthreads();

    for (int w = tid; w < 512; w += 256) {
        float2 v0 = d[0][phys(w)], v1 = d[1][phys(w)];
        float2 v2 = d[2][phys(w)], v3 = d[3][phys(w)];
        float4* p = (float4*)&g_bufA[((size_t)img * HP + w) * HH + row0];
        p[0] = make_float4(v0.x, v0.y, v1.x, v1.y);
        p[1] = make_float4(v2.x, v2.y, v3.x, v3.y);
    }
}

// ---------------------------------------------------------------------------
// k_fused: warp-synchronous 16pt/thread column FFT + mix + inverse.
// (320,2), register-only pad/crop fold. (R16-exact — measured best)
// ---------------------------------------------------------------------------
__global__ void __launch_bounds__(320, 2)
k_fused() {
    __shared__ float2 d[10][PH2];
    __shared__ float2 tw[256];
    int tid = threadIdx.x;
    if (tid < 256) { float sv, cv; sincospif(-(float)tid / 256.0f, &sv, &cv); tw[tid] = make_float2(cv, sv); }

    int bid = blockIdx.x;
    int nc = bid % (NN * CC);
    int w0 = (bid / (NN * CC)) * 2;

    int wid = tid >> 5, lane = tid & 31;
    int arr = wid >> 1, col = wid & 1;
    int img = nc * AA + arr;
    int rev5L = (int)(__brev((unsigned)lane) >> 27);
    float2* D = d[wid];
    const float2* in = &g_bufA[((size_t)img * HP + w0 + col) * HH];

    // load nonzero inputs and construct post-stage-1 registers directly
    float2 r[16];
    {
        float2 v1  = in[128 + rev5L];
        float2 v2  = in[  0 + rev5L];
        float2 v5  = in[192 + rev5L];
        float2 v6  = in[ 64 + rev5L];
        float2 v9  = in[160 + rev5L];
        float2 v10 = in[ 32 + rev5L];
        float2 v13 = in[224 + rev5L];
        float2 v14 = in[ 96 + rev5L];
        r[0] = v1;  r[1] = make_float2(-v1.x, -v1.y);
        r[2] = v2;  r[3] = v2;
        r[4] = v5;  r[5] = make_float2(-v5.x, -v5.y);
        r[6] = v6;  r[7] = v6;
        r[8] = v9;  r[9] = make_float2(-v9.x, -v9.y);
        r[10] = v10; r[11] = v10;
        r[12] = v13; r[13] = make_float2(-v13.x, -v13.y);
        r[14] = v14; r[15] = v14;
    }
    __syncthreads();

    // forward stages 2-4
    #pragma unroll
    for (int s = 2; s <= 4; s++) {
        int half = 1 << (s - 1);
        #pragma unroll
        for (int i = 0; i < 16; i++) if (!(i & half)) {
            float2 w = tw[((i & (half - 1)) << (9 - s)) & 255];
            float2 t = cmul(r[i + half], w);
            float2 A = r[i];
            r[i]        = make_float2(A.x + t.x, A.y + t.y);
            r[i + half] = make_float2(A.x - t.x, A.y - t.y);
        }
    }
    #pragma unroll
    for (int i = 0; i < 16; i++) D[phys2(16 * lane + i)] = r[i];
    __syncwarp();

    // forward stages 5-8
    int g = lane >> 4, u = lane & 15;
    int bbase = 256 * g + u;
    #pragma unroll
    for (int m = 0; m < 16; m++) r[m] = D[phys2(bbase + 16 * m)];
    #pragma unroll
    for (int s = 5; s <= 8; s++) {
        int hm = 1 << (s - 5);
        #pragma unroll
        for (int m = 0; m < 16; m++) if (!(m & hm)) {
            float2 w = tw[((u + 16 * (m & (hm - 1))) << (9 - s)) & 255];
            float2 t = cmul(r[m + hm], w);
            float2 A = r[m];
            r[m]      = make_float2(A.x + t.x, A.y + t.y);
            r[m + hm] = make_float2(A.x - t.x, A.y - t.y);
        }
    }
    #pragma unroll
    for (int m = 0; m < 16; m++) D[phys2(bbase + 16 * m)] = r[m];
    __syncwarp();

    // forward stage 9
    #pragma unroll
    for (int jj = 0; jj < 8; jj++) {
        int p = 8 * lane + jj;
        float2 A = D[phys2(p)], B = D[phys2(p + 256)];
        float2 t = cmul(B, tw[p]);
        D[phys2(p)]       = make_float2(A.x + t.x, A.y + t.y);
        D[phys2(p + 256)] = make_float2(A.x - t.x, A.y - t.y);
    }
    __syncthreads();

    // mix
    for (int i = tid; i < 2 * 512; i += 320) {
        int mcol = i >> 9, t = i & 511;
        size_t kbase = (size_t)(w0 + mcol) * HP + t;
        float2 F[5], G[5];
        #pragma unroll
        for (int a2 = 0; a2 < 5; a2++) F[a2] = d[a2 * 2 + mcol][phys2(t)];
        #pragma unroll
        for (int b = 0; b < 5; b++) {
            float2 acc = make_float2(0.f, 0.f);
            #pragma unroll
            for (int a2 = 0; a2 < 5; a2++) {
                float2 K = g_kT[(size_t)(b * 5 + a2) * NPIX + kbase];
                acc.x += K.x * F[a2].x - K.y * F[a2].y;
                acc.y += K.x * F[a2].y + K.y * F[a2].x;
            }
            G[b] = acc;
        }
        #pragma unroll
        for (int b = 0; b < 5; b++) d[b * 2 + mcol][phys2(t)] = G[b];
    }
    __syncthreads();

    // inverse stage 9
    #pragma unroll
    for (int jj = 0; jj < 8; jj++) {
        int p = 8 * lane + jj;
        float2 A = D[phys2(p)], B = D[phys2(p + 256)];
        float2 w = tw[p]; w.y = -w.y;
        float2 dd = make_float2(A.x - B.x, A.y - B.y);
        D[phys2(p)]       = make_float2(A.x + B.x, A.y + B.y);
        D[phys2(p + 256)] = cmul(dd, w);
    }
    __syncwarp();

    // inverse stages 8..5
    #pragma unroll
    for (int m = 0; m < 16; m++) r[m] = D[phys2(bbase + 16 * m)];
    #pragma unroll
    for (int s = 8; s >= 5; s--) {
        int hm = 1 << (s - 5);
        #pragma unroll
        for (int m = 0; m < 16; m++) if (!(m & hm)) {
            float2 w = tw[((u + 16 * (m & (hm - 1))) << (9 - s)) & 255]; w.y = -w.y;
            float2 A = r[m], B = r[m + hm];
            float2 dd = make_float2(A.x - B.x, A.y - B.y);
            r[m]      = make_float2(A.x + B.x, A.y + B.y);
            r[m + hm] = cmul(dd, w);
        }
    }
    #pragma unroll
    for (int m = 0; m < 16; m++) D[phys2(bbase + 16 * m)] = r[m];
    __syncwarp();

    // inverse stages 4..2, folded stage-1 + cropped store
    #pragma unroll
    for (int i = 0; i < 16; i++) r[i] = D[phys2(16 * lane + i)];
    #pragma unroll
    for (int s = 4; s >= 2; s--) {
        int half = 1 << (s - 1);
        #pragma unroll
        for (int i = 0; i < 16; i++) if (!(i & half)) {
            float2 w = tw[((i & (half - 1)) << (9 - s)) & 255]; w.y = -w.y;
            float2 A = r[i], B = r[i + half];
            float2 dd = make_float2(A.x - B.x, A.y - B.y);
            r[i]        = make_float2(A.x + B.x, A.y + B.y);
            r[i + half] = cmul(dd, w);
        }
    }
    const float sc = 1.0f / 512.0f;
    float2* outp = &g_bufA[((size_t)img * HP + w0 + col) * HH];
    outp[128 + rev5L] = make_float2((r[0].x - r[1].x) * sc,  (r[0].y - r[1].y) * sc);
    outp[  0 + rev5L] = make_float2((r[2].x + r[3].x) * sc,  (r[2].y + r[3].y) * sc);
    outp[192 + rev5L] = make_float2((r[4].x - r[5].x) * sc,  (r[4].y - r[5].y) * sc);
    outp[ 64 + rev5L] = make_float2((r[6].x + r[7].x) * sc,  (r[6].y + r[7].y) * sc);
    outp[160 + rev5L] = make_float2((r[8].x - r[9].x) * sc,  (r[8].y - r[9].y) * sc);
    outp[ 32 + rev5L] = make_float2((r[10].x + r[11].x) * sc,(r[10].y + r[11].y) * sc);
    outp[224 + rev5L] = make_float2((r[12].x - r[13].x) * sc,(r[12].y - r[13].y) * sc);
    outp[ 96 + rev5L] = make_float2((r[14].x + r[15].x) * sc,(r[14].y + r[15].y) * sc);
}

// ---------------------------------------------------------------------------
// k_i2: inverse row FFTs + crop + conj(mps) over half the coils.
// Block = (cg, n, b, 4 rows), 256 thr. (R14-exact — measured best: 93us)
// ---------------------------------------------------------------------------
__global__ void __launch_bounds__(256)
k_i2(const float* __restrict__ mr, const float* __restrict__ mi) {
    __shared__ float2 d[4][PH];
    __shared__ float2 tw[256];
    int tid = threadIdx.x;
    { float sv, cv; sincospif(-(float)tid / 256.0f, &sv, &cv); tw[tid] = make_float2(cv, sv); }

    int bid = blockIdx.x;
    int row0 = (bid & 63) * 4;
    int cgnb = bid >> 6;
    int cg = cgnb & 1;
    int nb = cgnb >> 1;
    int b = nb % AA;
    int n = nb / AA;

    int row = tid >> 6, lane = tid & 63;
    int bar = row + 1;

    float2 acc[4];
    #pragma unroll
    for (int k = 0; k < 4; k++) acc[k] = make_float2(0.f, 0.f);

    for (int ci = 0; ci < 6; ci++) {
        int c = cg * 6 + ci;
        int img = (n * CC + c) * AA + b;
        __syncthreads();
        for (int w = tid; w < 512; w += 256) {
            const float4* p = (const float4*)&g_bufA[((size_t)img * HP + w) * HH + row0];
            float4 q0 = p[0], q1 = p[1];
            d[0][phys(w)] = make_float2(q0.x, q0.y);
            d[1][phys(w)] = make_float2(q0.z, q0.w);
            d[2][phys(w)] = make_float2(q1.x, q1.y);
            d[3][phys(w)] = make_float2(q1.z, q1.w);
        }
        __syncthreads();

        reg_fft_phase<2,true>(d[row], lane, tw, -1.f); BAR64(bar);
        reg_fft_phase<1,true>(d[row], lane, tw, -1.f); BAR64(bar);
        reg_fft_phase<0,true>(d[row], lane, tw, -1.f); BAR64(bar);

        size_t moff = ((size_t)c * HH + row0 + row) * HH;
        #pragma unroll
        for (int k = 0; k < 4; k++) {
            int cw = lane + k * 64;
            float2 v = d[row][phys(brev9(128 + cw))];
            float m_r = mr[moff + cw], m_i = mi[moff + cw];
            acc[k].x += v.x * m_r + v.y * m_i;
            acc[k].y += v.y * m_r - v.x * m_i;
        }
    }

    size_t obase = ((size_t)(n * AA + b) * HH + row0 + row) * HH;
    #pragma unroll
    for (int k = 0; k < 4; k++) {
        g_part[(size_t)cg * SZ_X + obase + lane + k * 64] = acc[k];
    }
}

// ---------------------------------------------------------------------------
// k_comb: add coil-half partials, scale, planar output. (validated)
// ---------------------------------------------------------------------------
__global__ void __launch_bounds__(256)
k_comb(float* __restrict__ out, long out_floats) {
    size_t o = (size_t)blockIdx.x * 256 + threadIdx.x;
    float2 v0 = g_part[o], v1 = g_part[(size_t)SZ_X + o];
    const float sc = 4.0f / 512.0f;
    float re = (v0.x + v1.x) * sc;
    float im = (v0.y + v1.y) * sc;
    if ((long)o < out_floats) out[o] = re;
    if ((long)(SZ_X + o) < out_floats) out[SZ_X + o] = im;
}

// ---------------------------------------------------------------------------
// Input resolver (R7..R16-validated)
// ---------------------------------------------------------------------------
static void pick(void* const* d_in, const int* in_sizes, int n_in, long S,
                 int pos_split, const float** re, const float** im) {
    int idx[2] = {-1, -1};
    int cnt = 0;
    for (int i = 0; i < n_in; i++) {
        long v = (long)in_sizes[i];
        if (v == S || v == 2 * S || v == 4 * S || v == 8 * S) {
            if (cnt < 2) idx[cnt] = i;
            cnt++;
        }
    }
    if (cnt >= 2) {
        *re = (const float*)d_in[idx[0]];
        *im = (const float*)d_in[idx[1]];
    } else if (cnt == 1) {
        *re = (const float*)d_in[idx[0]];
        *im = *re + 1;
    } else {
        int p0 = (pos_split < n_in) ? pos_split : 0;
        int p1 = (pos_split + 1 < n_in) ? pos_split + 1 : p0;
        *re = (const float*)d_in[p0];
        *im = (const float*)d_in[p1];
    }
}

extern "C" void kernel_launch(void* const* d_in, const int* in_sizes, int n_in,
                              void* d_out, int out_size) {
    const float *xr, *xi, *mr, *mi, *kr, *ki;
    pick(d_in, in_sizes, n_in, SZ_X, 0, &xr, &xi);
    pick(d_in, in_sizes, n_in, SZ_M, 2, &mr, &mi);
    pick(d_in, in_sizes, n_in, SZ_K, 4, &kr, &ki);
    float* out = (float*)d_out;

    dim3 trg(16, 16, 25);
    k_tr<<<trg, 256>>>(kr, ki);
    k_f1<<<NIMG * 64, 256>>>(xr, xi, mr, mi);
    k_fused<<<(NN * CC) * (HP / 2), 320>>>();
    k_i2<<<NN * AA * 64 * 2, 256>>>(mr, mi);
    k_comb<<<(int)(SZ_X / 256), 256>>>(out, (long)out_size);
}